// round 17
// baseline (speedup 1.0000x reference)
#include <cuda_runtime.h>
#include <cuda_fp16.h>
#include <cstdint>

#define BB 16
#define NN 16384
#define CC 128
#define KK 9
#define TM 128
#define THREADS 512
#define NCHUNK_CONV 72          // 8 c8 * 9 ko, K=16 each
#define NCHUNK 80               // + 8 skip chunks
#define NREGION 40              // 2 chunks per region
#define REGION_GB 8192          // bytes per W region in global
#define ROW_SB 80               // smem row stride (64B data + 16B pad)
#define BUF_B (128 * ROW_SB)    // 10240 per region buffer
#define NBUF 4

// smem layout (bytes)
#define WBUF_OFF 0                          // 4 * 10240 = 40960
#define PD_OFF   (NBUF * BUF_B)             // 40960, 8*8*81*8 = 41472
#define IDX_OFF  (PD_OFF + 41472)           // 82432, 128*9*4 = 4608
#define BIAS_OFF (IDX_OFF + 4608)           // 87040, 256*4
#define SMEM_TOTAL (BIAS_OFF + 1024 + 128)  // 88192

// W pre-permuted fp16: [region 40][o 128][k 32] (two perm16'd k16 halves)
__device__ __align__(16) __half g_W2[NREGION * 128 * 32];
// dP = P - I as fp16 broadcast pairs: [npair 8192][k 9][j 9][h 2] uint32 {h,h}
__device__ __align__(16) uint32_t g_Pd[8192 * 81 * 2];

__host__ __device__ __forceinline__ int perm16(int p) {
    int e = p & 1;
    return (p < 8) ? ((p >> 1) * 4 + e) : (((p - 8) >> 1) * 4 + 2 + e);
}

__global__ void prep_w(const float* __restrict__ Wc, const float* __restrict__ Ws) {
    int t = blockIdx.x * blockDim.x + threadIdx.x;
    if (t < NREGION * 128 * 32) {
        int rg = t >> 12, rem = t & 4095, o = rem >> 5, kk = rem & 31;
        int ci = rg * 2 + (kk >> 4);
        int p  = kk & 15;
        float v;
        if (ci < NCHUNK_CONV) {
            int c8 = ci / 9, ko = ci % 9;
            v = Wc[o * 1152 + ko * CC + c8 * 16 + perm16(p)];
        } else {
            int cs = ci - NCHUNK_CONV;
            v = Ws[o * CC + cs * 16 + perm16(p)];
        }
        g_W2[t] = __float2half_rn(v);
    }
}

__global__ void prep_pd(const float* __restrict__ P) {
    int t = blockIdx.x * blockDim.x + threadIdx.x;
    if (t < NN * 81) {
        int n = t / 81, rem = t - n * 81;
        int k = rem / 9, j = rem - k * 9;
        float v = P[t] - ((k == j) ? 1.0f : 0.0f);
        __half h = __float2half_rn(v);
        __half2 hh = __half2half2(h);
        int np = (n >> 4) * 8 + (n & 7);
        int hs = (n >> 3) & 1;
        g_Pd[(np * 81 + rem) * 2 + hs] = *reinterpret_cast<uint32_t*>(&hh);
    }
}

// ---------------- PTX helpers ----------------
__device__ __forceinline__ uint32_t smem_u32(const void* p) {
    uint32_t a;
    asm("{ .reg .u64 t; cvta.to.shared.u64 t, %1; cvt.u32.u64 %0, t; }" : "=r"(a) : "l"(p));
    return a;
}
#define CP_ASYNC16(dst, src) \
    asm volatile("cp.async.cg.shared.global [%0], [%1], 16;" :: "r"(dst), "l"(src))
#define CP_COMMIT() asm volatile("cp.async.commit_group;" ::: "memory")
#define CP_WAIT(n)  asm volatile("cp.async.wait_group %0;" :: "n"(n) : "memory")

__device__ __forceinline__ void ldsm_x4(uint32_t* r, uint32_t addr) {
    asm volatile("ldmatrix.sync.aligned.m8n8.x4.shared.b16 {%0,%1,%2,%3}, [%4];"
                 : "=r"(r[0]), "=r"(r[1]), "=r"(r[2]), "=r"(r[3]) : "r"(addr));
}
__device__ __forceinline__ void mma16816(float* c, const uint32_t* a,
                                         uint32_t b0, uint32_t b1) {
    asm volatile("mma.sync.aligned.m16n8k16.row.col.f32.f16.f16.f32 "
                 "{%0,%1,%2,%3}, {%4,%5,%6,%7}, {%8,%9}, {%0,%1,%2,%3};"
                 : "+f"(c[0]), "+f"(c[1]), "+f"(c[2]), "+f"(c[3])
                 : "r"(a[0]), "r"(a[1]), "r"(a[2]), "r"(a[3]), "r"(b0), "r"(b1));
}
__device__ __forceinline__ float elu(float v) {
    float e;
    asm("ex2.approx.f32 %0, %1;" : "=f"(e) : "f"(v * 1.44269504f));
    return v > 0.f ? v : e - 1.f;
}
__device__ __forceinline__ uint32_t h2pack(float a, float b) {
    __half2 h = __floats2half2_rn(a, b);
    return *reinterpret_cast<uint32_t*>(&h);
}

// region fetch: 8KB, 512 threads x 16B, ONE commit
__device__ __forceinline__ void issue_region(uint32_t wbase, int rg, int tid) {
    const char* src = (const char*)g_W2 + (size_t)rg * REGION_GB;
    int o = tid >> 2, part = tid & 3;        // 4 x 16B per 64B row
    uint32_t dst = wbase + (rg & (NBUF - 1)) * BUF_B + o * ROW_SB + part * 16;
    CP_ASYNC16(dst, src + o * 64 + part * 16);
    CP_COMMIT();
}

__global__ __launch_bounds__(THREADS, 1)
void paiconv_ns(const float* __restrict__ x, const int* __restrict__ idxg,
                const float* __restrict__ P, const float* __restrict__ b_conv,
                const float* __restrict__ b_skip, float* __restrict__ out)
{
    extern __shared__ char smem[];
    const uint32_t sb = smem_u32(smem);
    const int tid  = threadIdx.x;
    const int lane = tid & 31;
    const int wid  = tid >> 5;               // 0..15
    const int n0   = blockIdx.x * TM;
    const int b    = blockIdx.y;

    int*   s_idx  = (int*)(smem + IDX_OFF);
    float* s_bias = (float*)(smem + BIAS_OFF);

    // start W pipeline: regions 0,1,2
    issue_region(sb + WBUF_OFF, 0, tid);
    issue_region(sb + WBUF_OFF, 1, tid);
    issue_region(sb + WBUF_OFF, 2, tid);

    // stage dP pairs (contiguous copy from g_Pd), idx, bias
    {
        const uint4* src = (const uint4*)(g_Pd + (size_t)(blockIdx.x * 64) * 162);
        uint4* dst = (uint4*)(smem + PD_OFF);
        for (int t = tid; t < 41472 / 16; t += THREADS) dst[t] = src[t];
    }
    for (int t = tid; t < TM * KK; t += THREADS) s_idx[t] = idxg[n0 * KK + t];
    if (tid < CC) { s_bias[tid] = b_conv[tid]; s_bias[CC + tid] = b_skip[tid]; }
    __syncthreads();

    const float* xb = x + (size_t)b * NN * CC;

    // roles: m-tile mt = wid>>1, n-half ncol = (wid&1)*64
    const int mt   = wid >> 1;
    const int ncol = (wid & 1) * 64;
    const int sN   = lane >> 2;              // row-slot within m16
    const int r0l  = mt * 16 + sN;           // local node
    const int r1l  = r0l + 8;
    const int q4   = (lane & 3) * 16;        // byte offset of lane's float4

    float acc[32];
    #pragma unroll
    for (int i = 0; i < 32; i++) acc[i] = 0.f;

    __half2 xh[KK][2][2];                    // [nbr][row][ch-pair]
    const uint32_t ldsm_base = sb + WBUF_OFF + (ncol + (lane & 15)) * ROW_SB + (lane >> 4) * 16;
    const char* pdbase = smem + PD_OFF + mt * 5184 + sN * 648;

    // ---------------- conv: 72 chunks (c8 outer, ko inner) ----------------
    int ci = 0;
    for (int c8 = 0; c8 < 8; c8++) {
        // gather channel-slice for 2 rows x 9 neighbors -> fp16 pairs (reused 9x)
        #pragma unroll
        for (int j = 0; j < KK; j++) {
            int ix0 = s_idx[r0l * KK + j];
            int ix1 = s_idx[r1l * KK + j];
            float4 v0 = make_float4(0.f, 0.f, 0.f, 0.f);
            float4 v1 = v0;
            if ((unsigned)ix0 < (unsigned)NN)
                v0 = __ldg((const float4*)((const char*)xb + (size_t)ix0 * 512 + c8 * 64 + q4));
            if ((unsigned)ix1 < (unsigned)NN)
                v1 = __ldg((const float4*)((const char*)xb + (size_t)ix1 * 512 + c8 * 64 + q4));
            xh[j][0][0] = __floats2half2_rn(v0.x, v0.y);
            xh[j][0][1] = __floats2half2_rn(v0.z, v0.w);
            xh[j][1][0] = __floats2half2_rn(v1.x, v1.y);
            xh[j][1][1] = __floats2half2_rn(v1.z, v1.w);
        }
        #pragma unroll
        for (int ko = 0; ko < 9; ko++, ci++) {
            if ((ci & 1) == 0) {
                if (ci < 74) { CP_WAIT(2); } else if (ci == 74) { CP_WAIT(1); } else { CP_WAIT(0); }
                __syncthreads();
                int rg = (ci >> 1) + 3;
                if (rg < NREGION) issue_region(sb + WBUF_OFF, rg, tid);
            }

            // mix: out = x_ko + sum_j dP[ko][j] * x_j  (half2, identity split)
            const uint2* pd = (const uint2*)(pdbase + ko * 72);
            __half2 m00 = __float2half2_rn(0.f), m01 = m00, m10 = m00, m11 = m00;
            #pragma unroll
            for (int j = 0; j < KK; j++) {
                uint2 p = pd[j];
                __half2 p0 = *reinterpret_cast<__half2*>(&p.x);
                __half2 p1 = *reinterpret_cast<__half2*>(&p.y);
                m00 = __hfma2(p0, xh[j][0][0], m00);
                m01 = __hfma2(p0, xh[j][0][1], m01);
                m10 = __hfma2(p1, xh[j][1][0], m10);
                m11 = __hfma2(p1, xh[j][1][1], m11);
            }
            m00 = __hadd2(xh[ko][0][0], m00);
            m01 = __hadd2(xh[ko][0][1], m01);
            m10 = __hadd2(xh[ko][1][0], m10);
            m11 = __hadd2(xh[ko][1][1], m11);

            float2 f00 = __half22float2(m00);
            float2 f01 = __half22float2(m01);
            float2 f10 = __half22float2(m10);
            float2 f11 = __half22float2(m11);

            uint32_t a[4];
            a[0] = h2pack(elu(f00.x), elu(f00.y));
            a[1] = h2pack(elu(f10.x), elu(f10.y));
            a[2] = h2pack(elu(f01.x), elu(f01.y));
            a[3] = h2pack(elu(f11.x), elu(f11.y));

            const uint32_t wb = ldsm_base + ((ci >> 1) & (NBUF - 1)) * BUF_B + (ci & 1) * 32;
            #pragma unroll
            for (int g = 0; g < 4; g++) {
                uint32_t bf[4];
                ldsm_x4(bf, wb + g * 16 * ROW_SB);
                mma16816(acc + (2 * g) * 4,     a, bf[0], bf[2]);
                mma16816(acc + (2 * g + 1) * 4, a, bf[1], bf[3]);
            }
        }
    }

    // ---------------- fold: acc = elu(acc + bc) + bs ----------------
    {
        const int cbase = (lane & 3) * 2;
        #pragma unroll
        for (int t = 0; t < 8; t++) {
            int col = ncol + t * 8 + cbase;
            float2 bc  = *(const float2*)(s_bias + col);
            float2 bs2 = *(const float2*)(s_bias + 128 + col);
            acc[t * 4 + 0] = elu(acc[t * 4 + 0] + bc.x) + bs2.x;
            acc[t * 4 + 1] = elu(acc[t * 4 + 1] + bc.y) + bs2.y;
            acc[t * 4 + 2] = elu(acc[t * 4 + 2] + bc.x) + bs2.x;
            acc[t * 4 + 3] = elu(acc[t * 4 + 3] + bc.y) + bs2.y;
        }
    }

    // ---------------- skip: 8 chunks, A = x directly ----------------
    for (int c8 = 0; c8 < 8; c8++, ci++) {
        if ((ci & 1) == 0) {
            if (ci < 74) { CP_WAIT(2); } else if (ci == 74) { CP_WAIT(1); } else { CP_WAIT(0); }
            __syncthreads();
            int rg = (ci >> 1) + 3;
            if (rg < NREGION) issue_region(sb + WBUF_OFF, rg, tid);
        }

        float4 v0 = __ldg((const float4*)((const char*)xb + (size_t)(n0 + r0l) * 512 + c8 * 64 + q4));
        float4 v1 = __ldg((const float4*)((const char*)xb + (size_t)(n0 + r1l) * 512 + c8 * 64 + q4));
        uint32_t a[4];
        a[0] = h2pack(v0.x, v0.y);
        a[1] = h2pack(v1.x, v1.y);
        a[2] = h2pack(v0.z, v0.w);
        a[3] = h2pack(v1.z, v1.w);

        const uint32_t wb = ldsm_base + ((ci >> 1) & (NBUF - 1)) * BUF_B + (ci & 1) * 32;
        #pragma unroll
        for (int g = 0; g < 4; g++) {
            uint32_t bf[4];
            ldsm_x4(bf, wb + g * 16 * ROW_SB);
            mma16816(acc + (2 * g) * 4,     a, bf[0], bf[2]);
            mma16816(acc + (2 * g + 1) * 4, a, bf[1], bf[3]);
        }
    }

    // ---------------- epilogue: store ----------------
    {
        const int cbase = (lane & 3) * 2;
        float* o0 = out + ((size_t)b * NN + n0 + r0l) * CC + ncol + cbase;
        float* o1 = out + ((size_t)b * NN + n0 + r1l) * CC + ncol + cbase;
        #pragma unroll
        for (int t = 0; t < 8; t++) {
            *(float2*)(o0 + t * 8) = make_float2(acc[t * 4 + 0], acc[t * 4 + 1]);
            *(float2*)(o1 + t * 8) = make_float2(acc[t * 4 + 2], acc[t * 4 + 3]);
        }
    }
}

extern "C" void kernel_launch(void* const* d_in, const int* in_sizes, int n_in,
                              void* d_out, int out_size) {
    const float* x       = (const float*)d_in[0];
    const int*   indices = (const int*)  d_in[1];
    const float* P       = (const float*)d_in[2];
    const float* W_conv  = (const float*)d_in[3];
    const float* b_conv  = (const float*)d_in[4];
    const float* W_skip  = (const float*)d_in[5];
    const float* b_skip  = (const float*)d_in[6];
    float* out = (float*)d_out;

    prep_w<<<(NREGION * 128 * 32 + 255) / 256, 256>>>(W_conv, W_skip);
    prep_pd<<<(NN * 81 + 255) / 256, 256>>>(P);

    cudaFuncSetAttribute(paiconv_ns,
                         cudaFuncAttributeMaxDynamicSharedMemorySize, SMEM_TOTAL);
    dim3 grid(NN / TM, BB);
    paiconv_ns<<<grid, THREADS, SMEM_TOTAL>>>(x, indices, P, b_conv, b_skip, out);
}